// round 3
// baseline (speedup 1.0000x reference)
#include <cuda_runtime.h>
#include <cstdint>

#define N_EVENT_C 100000
#define N_TRACE_C 20000
#define DIM 128
#define B_GRAPH 64
#define OUT_DIM 64

// ---------------- scratch (device globals: no allocations allowed) ----------------
__device__ float g_xe0[N_EVENT_C * DIM];
__device__ float g_xe1[N_EVENT_C * DIM];
__device__ float g_xt0[N_TRACE_C * DIM];
__device__ float g_xt1[N_TRACE_C * DIM];
__device__ float g_agg_ee[N_EVENT_C * DIM];
__device__ float g_agg_te[N_EVENT_C * DIM];
__device__ float g_agg_et[N_TRACE_C * DIM];
__device__ float g_yt[N_TRACE_C * DIM];
__device__ float g_inv_ee[N_EVENT_C];
__device__ float g_inv_te[N_EVENT_C];
__device__ float g_inv_et[N_TRACE_C];
__device__ float g_Bt_e[256 * 128];   // [k][j]: k<128 -> Wl0[j][k], k>=128 -> (Wr0+Wr2)[j][k-128]
__device__ float g_Bt_t[256 * 128];   // [k][j]: k<128 -> Wl1[j][k], k>=128 -> Wr1[j][k-128]
__device__ float g_Bt_y[128 * 128];   // [k][j]: Wl2[j][k]
__device__ float g_bias_e[128];
__device__ float g_bias_t[128];
__device__ float g_pooled[B_GRAPH * DIM];

static inline int cdiv(int a, int b) { return (a + b - 1) / b; }

// ---------------- small kernels ----------------

__global__ void degree_kernel(const int* __restrict__ dst, int E, float* __restrict__ deg) {
    int i = blockIdx.x * blockDim.x + threadIdx.x;
    if (i < E) atomicAdd(&deg[dst[i]], 1.0f);
}

__global__ void inv_kernel(float* __restrict__ deg, int N) {
    int i = blockIdx.x * blockDim.x + threadIdx.x;
    if (i < N) deg[i] = 1.0f / fmaxf(deg[i], 1.0f);
}

// out[i][:] = emb[ids[i]][:]
__global__ void gather_rows(const float* __restrict__ emb, const int* __restrict__ ids,
                            int N, float* __restrict__ out) {
    int idx = blockIdx.x * blockDim.x + threadIdx.x; // over N*32 float4
    if (idx < N * 32) {
        int i = idx >> 5;
        int j = idx & 31;
        ((float4*)out)[idx] = ((const float4*)(emb + (size_t)ids[i] * DIM))[j];
    }
}

// one warp per edge: agg[dst] += feat[src]  (vectorized global reduction)
__global__ void scatter_add_kernel(const float* __restrict__ feat,
                                   const int* __restrict__ src,
                                   const int* __restrict__ dst,
                                   int E, float* __restrict__ agg) {
    int w = (blockIdx.x * blockDim.x + threadIdx.x) >> 5;
    int lane = threadIdx.x & 31;
    if (w >= E) return;
    int s = __ldg(&src[w]);
    int d = __ldg(&dst[w]);
    float4 v = ((const float4*)(feat + (size_t)s * DIM))[lane];
    float* p = agg + (size_t)d * DIM + lane * 4;
    asm volatile("red.global.add.v4.f32 [%0], {%1,%2,%3,%4};"
                 :: "l"(p), "f"(v.x), "f"(v.y), "f"(v.z), "f"(v.w) : "memory");
}

// Build transposed/merged per-layer weight blocks + biases.
__global__ void prep_weights(const float* __restrict__ Wl, const float* __restrict__ bl,
                             const float* __restrict__ Wr, int l,
                             float* __restrict__ Bt_e, float* __restrict__ Bt_t,
                             float* __restrict__ Bt_y, float* __restrict__ bias_e,
                             float* __restrict__ bias_t) {
    int idx = blockIdx.x * blockDim.x + threadIdx.x;
    const float* Wl_l = Wl + (size_t)l * 3 * 16384;
    const float* Wr_l = Wr + (size_t)l * 3 * 16384;
    const float* bl_l = bl + (size_t)l * 3 * 128;
    if (idx < 32768) {                           // Bt_e
        int k = idx >> 7, j = idx & 127;
        if (k < 128)
            Bt_e[idx] = Wl_l[0 * 16384 + j * 128 + k];
        else
            Bt_e[idx] = Wr_l[0 * 16384 + j * 128 + (k - 128)] +
                        Wr_l[2 * 16384 + j * 128 + (k - 128)];
    } else if (idx < 65536) {                    // Bt_t
        int t = idx - 32768;
        int k = t >> 7, j = t & 127;
        if (k < 128)
            Bt_t[t] = Wl_l[1 * 16384 + j * 128 + k];
        else
            Bt_t[t] = Wr_l[1 * 16384 + j * 128 + (k - 128)];
    } else if (idx < 81920) {                    // Bt_y
        int t = idx - 65536;
        int k = t >> 7, j = t & 127;
        Bt_y[t] = Wl_l[2 * 16384 + j * 128 + k];
    } else if (idx < 81920 + 128) {
        int j = idx - 81920;
        bias_e[j] = bl_l[0 * 128 + j] + bl_l[2 * 128 + j];
    } else if (idx < 81920 + 256) {
        int j = idx - 82048;
        bias_t[j] = bl_l[1 * 128 + j];
    }
}

// ---------------- fused GEMM ----------------
// C[i][j] = sum_k<128 (A1[i][k]*s1[i]) * Bt[k][j]
//         + (kseg==2) sum_k A2[i][k] * Bt[128+k][j]
//         + (addm)    addm[i][j]*adds[i]
//         + (bias)    bias[j]
// Bt is [K][128] (pre-transposed). BM=BN=128, BK=8, 256 threads, 8x8/thread.
__global__ void __launch_bounds__(256)
gemm_fused(const float* __restrict__ A1, const float* __restrict__ s1,
           const float* __restrict__ A2,
           const float* __restrict__ Bt,
           const float* __restrict__ addm, const float* __restrict__ adds,
           const float* __restrict__ bias,
           float* __restrict__ C, int M, int kseg) {
    __shared__ float As[8][128];
    __shared__ float Bs[8][128];

    int tid = threadIdx.x;
    int tx = tid & 15, ty = tid >> 4;
    int row0 = blockIdx.x * 128;

    float acc[8][8];
#pragma unroll
    for (int i = 0; i < 8; i++)
#pragma unroll
        for (int j = 0; j < 8; j++) acc[i][j] = 0.0f;

    // A-load mapping: each thread one float4
    int ar = tid >> 1;                  // 0..127
    int ak4 = (tid & 1) * 4;            // 0 or 4
    int arow = row0 + ar;
    float ascale = 1.0f;
    if (arow < M && s1) ascale = s1[arow];
    // B-load mapping
    int bk = tid >> 5;                  // 0..7
    int bj = (tid & 31) * 4;            // 0..124

    int KT = kseg * 128;
    for (int k0 = 0; k0 < KT; k0 += 8) {
        float4 av = make_float4(0.f, 0.f, 0.f, 0.f);
        if (arow < M) {
            int k = k0 + ak4;
            if (k < 128) {
                av = *(const float4*)(A1 + (size_t)arow * DIM + k);
                av.x *= ascale; av.y *= ascale; av.z *= ascale; av.w *= ascale;
            } else {
                av = *(const float4*)(A2 + (size_t)arow * DIM + (k - 128));
            }
        }
        float4 bv = *(const float4*)(Bt + (size_t)(k0 + bk) * 128 + bj);

        __syncthreads();
        As[ak4 + 0][ar] = av.x;
        As[ak4 + 1][ar] = av.y;
        As[ak4 + 2][ar] = av.z;
        As[ak4 + 3][ar] = av.w;
        *(float4*)&Bs[bk][bj] = bv;
        __syncthreads();

#pragma unroll
        for (int kk = 0; kk < 8; kk++) {
            float4 a0 = *(float4*)&As[kk][ty * 4];
            float4 a1 = *(float4*)&As[kk][64 + ty * 4];
            float4 b0 = *(float4*)&Bs[kk][tx * 4];
            float4 b1 = *(float4*)&Bs[kk][64 + tx * 4];
            float a[8] = {a0.x, a0.y, a0.z, a0.w, a1.x, a1.y, a1.z, a1.w};
            float b[8] = {b0.x, b0.y, b0.z, b0.w, b1.x, b1.y, b1.z, b1.w};
#pragma unroll
            for (int ri = 0; ri < 8; ri++)
#pragma unroll
                for (int ci = 0; ci < 8; ci++) acc[ri][ci] += a[ri] * b[ci];
        }
    }

    int c0 = tx * 4, c1 = 64 + tx * 4;
    float4 bia0 = make_float4(0.f, 0.f, 0.f, 0.f);
    float4 bia1 = make_float4(0.f, 0.f, 0.f, 0.f);
    if (bias) {
        bia0 = *(const float4*)(bias + c0);
        bia1 = *(const float4*)(bias + c1);
    }
#pragma unroll
    for (int ri = 0; ri < 8; ri++) {
        int rr = (ri < 4) ? (ty * 4 + ri) : (64 + ty * 4 + (ri - 4));
        int row = row0 + rr;
        if (row >= M) continue;
        float4 o0 = make_float4(acc[ri][0] + bia0.x, acc[ri][1] + bia0.y,
                                acc[ri][2] + bia0.z, acc[ri][3] + bia0.w);
        float4 o1 = make_float4(acc[ri][4] + bia1.x, acc[ri][5] + bia1.y,
                                acc[ri][6] + bia1.z, acc[ri][7] + bia1.w);
        if (addm) {
            float s = adds[row];
            float4 m0 = *(const float4*)(addm + (size_t)row * DIM + c0);
            float4 m1 = *(const float4*)(addm + (size_t)row * DIM + c1);
            o0.x += m0.x * s; o0.y += m0.y * s; o0.z += m0.z * s; o0.w += m0.w * s;
            o1.x += m1.x * s; o1.y += m1.y * s; o1.z += m1.z * s; o1.w += m1.w * s;
        }
        float* crow = C + (size_t)row * DIM;
        *(float4*)(crow + c0) = o0;
        *(float4*)(crow + c1) = o1;
    }
}

// ---------------- pooling (batch sorted; run-length accumulate, atomic flush) ----------------
#define POOL_ROWS 512
__global__ void pool_kernel(const float* __restrict__ x, const int* __restrict__ batch,
                            int N, float* __restrict__ pooled) {
    int j = threadIdx.x;            // 0..127
    int r0 = blockIdx.x * POOL_ROWS;
    if (r0 >= N) return;
    int r1 = min(r0 + POOL_ROWS, N);
    float acc = 0.0f;
    int cur = batch[r0];
    for (int r = r0; r < r1; r++) {
        int b = batch[r];
        if (b != cur) {
            atomicAdd(&pooled[cur * DIM + j], acc);
            acc = 0.0f;
            cur = b;
        }
        acc += x[(size_t)r * DIM + j];
    }
    atomicAdd(&pooled[cur * DIM + j], acc);
}

// ---------------- MLP head: out[b] = relu(pooled[b]@W1.T + b1) @ W2.T + b2 ----------------
__global__ void mlp_kernel(const float* __restrict__ pooled,
                           const float* __restrict__ W1, const float* __restrict__ b1,
                           const float* __restrict__ W2, const float* __restrict__ b2,
                           float* __restrict__ out) {
    int b = blockIdx.x;
    int t = threadIdx.x;   // 128
    __shared__ float p[128], h[128];
    p[t] = pooled[b * DIM + t];
    __syncthreads();
    float acc = b1[t];
#pragma unroll 8
    for (int k = 0; k < 128; k++) acc += p[k] * W1[t * 128 + k];
    h[t] = fmaxf(acc, 0.0f);
    __syncthreads();
    if (t < OUT_DIM) {
        float o = b2[t];
#pragma unroll 8
        for (int k = 0; k < 128; k++) o += h[k] * W2[t * 128 + k];
        out[b * OUT_DIM + t] = o;
    }
}

// ---------------- driver ----------------
extern "C" void kernel_launch(void* const* d_in, const int* in_sizes, int n_in,
                              void* d_out, int out_size) {
    const int* event_ids   = (const int*)d_in[0];
    const int* trace_ids   = (const int*)d_in[1];
    const int* e2e_src     = (const int*)d_in[2];
    const int* e2e_dst     = (const int*)d_in[3];
    const int* e2t_src     = (const int*)d_in[4];
    const int* e2t_dst     = (const int*)d_in[5];
    const int* t2e_src     = (const int*)d_in[6];
    const int* t2e_dst     = (const int*)d_in[7];
    const int* event_batch = (const int*)d_in[8];
    const int* trace_batch = (const int*)d_in[9];
    const float* emb_event = (const float*)d_in[10];
    const float* emb_trace = (const float*)d_in[11];
    const float* Wl        = (const float*)d_in[12];
    const float* bl        = (const float*)d_in[13];
    const float* Wr        = (const float*)d_in[14];
    const float* W1        = (const float*)d_in[15];
    const float* b1        = (const float*)d_in[16];
    const float* W2        = (const float*)d_in[17];
    const float* b2        = (const float*)d_in[18];

    const int Ne  = in_sizes[0];
    const int Nt  = in_sizes[1];
    const int Eee = in_sizes[2];
    const int Eet = in_sizes[4];
    const int Ete = in_sizes[6];

    float *xe[2], *xt[2], *agg_ee, *agg_te, *agg_et, *yt;
    float *inv_ee, *inv_te, *inv_et, *Bt_e, *Bt_t, *Bt_y, *bias_e, *bias_t, *pooled;
    cudaGetSymbolAddress((void**)&xe[0], g_xe0);
    cudaGetSymbolAddress((void**)&xe[1], g_xe1);
    cudaGetSymbolAddress((void**)&xt[0], g_xt0);
    cudaGetSymbolAddress((void**)&xt[1], g_xt1);
    cudaGetSymbolAddress((void**)&agg_ee, g_agg_ee);
    cudaGetSymbolAddress((void**)&agg_te, g_agg_te);
    cudaGetSymbolAddress((void**)&agg_et, g_agg_et);
    cudaGetSymbolAddress((void**)&yt, g_yt);
    cudaGetSymbolAddress((void**)&inv_ee, g_inv_ee);
    cudaGetSymbolAddress((void**)&inv_te, g_inv_te);
    cudaGetSymbolAddress((void**)&inv_et, g_inv_et);
    cudaGetSymbolAddress((void**)&Bt_e, g_Bt_e);
    cudaGetSymbolAddress((void**)&Bt_t, g_Bt_t);
    cudaGetSymbolAddress((void**)&Bt_y, g_Bt_y);
    cudaGetSymbolAddress((void**)&bias_e, g_bias_e);
    cudaGetSymbolAddress((void**)&bias_t, g_bias_t);
    cudaGetSymbolAddress((void**)&pooled, g_pooled);

    // ---- degrees (layer-invariant) ----
    cudaMemsetAsync(inv_ee, 0, (size_t)Ne * sizeof(float));
    cudaMemsetAsync(inv_te, 0, (size_t)Ne * sizeof(float));
    cudaMemsetAsync(inv_et, 0, (size_t)Nt * sizeof(float));
    cudaMemsetAsync(pooled, 0, (size_t)B_GRAPH * DIM * sizeof(float));
    degree_kernel<<<cdiv(Eee, 256), 256>>>(e2e_dst, Eee, inv_ee);
    degree_kernel<<<cdiv(Ete, 256), 256>>>(t2e_dst, Ete, inv_te);
    degree_kernel<<<cdiv(Eet, 256), 256>>>(e2t_dst, Eet, inv_et);
    inv_kernel<<<cdiv(Ne, 256), 256>>>(inv_ee, Ne);
    inv_kernel<<<cdiv(Ne, 256), 256>>>(inv_te, Ne);
    inv_kernel<<<cdiv(Nt, 256), 256>>>(inv_et, Nt);

    // ---- initial embeddings ----
    gather_rows<<<cdiv(Ne * 32, 256), 256>>>(emb_event, event_ids, Ne, xe[0]);
    gather_rows<<<cdiv(Nt * 32, 256), 256>>>(emb_trace, trace_ids, Nt, xt[0]);

    int cur = 0;
    for (int l = 0; l < 3; l++) {
        cudaMemsetAsync(agg_ee, 0, (size_t)Ne * DIM * sizeof(float));
        cudaMemsetAsync(agg_te, 0, (size_t)Ne * DIM * sizeof(float));
        cudaMemsetAsync(agg_et, 0, (size_t)Nt * DIM * sizeof(float));

        prep_weights<<<cdiv(82176, 256), 256>>>(Wl, bl, Wr, l, Bt_e, Bt_t, Bt_y, bias_e, bias_t);

        // transform-first for trace->event: y = x_trace @ Wl2.T
        gemm_fused<<<cdiv(Nt, 128), 256>>>(xt[cur], nullptr, nullptr, Bt_y,
                                           nullptr, nullptr, nullptr, yt, Nt, 1);

        // aggregations
        scatter_add_kernel<<<cdiv(Eee, 8), 256>>>(xe[cur], e2e_src, e2e_dst, Eee, agg_ee);
        scatter_add_kernel<<<cdiv(Eet, 8), 256>>>(xe[cur], e2t_src, e2t_dst, Eet, agg_et);
        scatter_add_kernel<<<cdiv(Ete, 8), 256>>>(yt, t2e_src, t2e_dst, Ete, agg_te);

        // event: mean_ee@Wl0.T + x_e@(Wr0+Wr2).T + mean(y over t2e) + (bl0+bl2)
        gemm_fused<<<cdiv(Ne, 128), 256>>>(agg_ee, inv_ee, xe[cur], Bt_e,
                                           agg_te, inv_te, bias_e, xe[1 - cur], Ne, 2);
        // trace: mean_et@Wl1.T + x_t@Wr1.T + bl1
        gemm_fused<<<cdiv(Nt, 128), 256>>>(agg_et, inv_et, xt[cur], Bt_t,
                                           nullptr, nullptr, bias_t, xt[1 - cur], Nt, 2);
        cur ^= 1;
    }

    // ---- pooling + head ----
    pool_kernel<<<cdiv(Ne, POOL_ROWS), 128>>>(xe[cur], event_batch, Ne, pooled);
    pool_kernel<<<cdiv(Nt, POOL_ROWS), 128>>>(xt[cur], trace_batch, Nt, pooled);
    mlp_kernel<<<B_GRAPH, 128>>>(pooled, W1, b1, W2, b2, (float*)d_out);
}

// round 4
// speedup vs baseline: 1.9671x; 1.9671x over previous
#include <cuda_runtime.h>
#include <cstdint>

#define N_EVENT_C 100000
#define N_TRACE_C 20000
#define E_EE_C 1000000
#define E_ET_C 500000
#define E_TE_C 500000
#define DIM 128
#define B_GRAPH 64
#define OUT_DIM 64

// ---------------- scratch (device globals: no allocations allowed) ----------------
__device__ float g_xe0[N_EVENT_C * DIM];
__device__ float g_xe1[N_EVENT_C * DIM];
__device__ float g_xt0[N_TRACE_C * DIM];
__device__ float g_xt1[N_TRACE_C * DIM];
__device__ float g_agg_ee[N_EVENT_C * DIM];
__device__ float g_agg_te[N_EVENT_C * DIM];
__device__ float g_agg_et[N_TRACE_C * DIM];
__device__ float g_yt[N_TRACE_C * DIM];

// CSR scratch per edge type
__device__ int g_cnt_ee[N_EVENT_C];
__device__ int g_cnt_te[N_EVENT_C];
__device__ int g_cnt_et[N_TRACE_C];
__device__ int g_rowp_ee[N_EVENT_C];
__device__ int g_rowp_te[N_EVENT_C];
__device__ int g_rowp_et[N_TRACE_C];
__device__ int g_cur_ee[N_EVENT_C];
__device__ int g_cur_te[N_EVENT_C];
__device__ int g_cur_et[N_TRACE_C];
__device__ int g_bsum_ee[1024];
__device__ int g_bsum_te[1024];
__device__ int g_bsum_et[1024];
__device__ int g_csr_ee[E_EE_C];
__device__ int g_csr_te[E_TE_C];
__device__ int g_csr_et[E_ET_C];

__device__ float g_Bt_e[256 * 128];   // [k][j]: k<128 -> Wl0[j][k], k>=128 -> (Wr0+Wr2)[j][k-128]
__device__ float g_Bt_t[256 * 128];   // [k][j]: k<128 -> Wl1[j][k], k>=128 -> Wr1[j][k-128]
__device__ float g_Bt_y[128 * 128];   // [k][j]: Wl2[j][k]
__device__ float g_bias_e[128];
__device__ float g_bias_t[128];
__device__ float g_pooled[B_GRAPH * DIM];

static inline int cdiv(int a, int b) { return (a + b - 1) / b; }

typedef unsigned long long u64c;

__device__ __forceinline__ u64c pk2(float lo, float hi) {
    u64c r;
    asm("mov.b64 %0, {%1, %2};" : "=l"(r) : "f"(lo), "f"(hi));
    return r;
}
__device__ __forceinline__ void fma2(u64c& d, u64c a, u64c b) {
    asm("fma.rn.f32x2 %0, %1, %2, %0;" : "+l"(d) : "l"(a), "l"(b));
}
__device__ __forceinline__ void upk2(u64c v, float& lo, float& hi) {
    asm("mov.b64 {%0, %1}, %2;" : "=f"(lo), "=f"(hi) : "l"(v));
}

// ---------------- CSR build kernels ----------------

__global__ void degree_int(const int* __restrict__ dst, int E, int* __restrict__ cnt) {
    int i = blockIdx.x * blockDim.x + threadIdx.x;
    if (i < E) atomicAdd(&cnt[dst[i]], 1);
}

// per-1024 block exclusive scan + block totals
__global__ void scan_block(const int* __restrict__ cnt, int N,
                           int* __restrict__ excl, int* __restrict__ bsum) {
    __shared__ int sh[1024];
    int tid = threadIdx.x;
    int i = blockIdx.x * 1024 + tid;
    int v = (i < N) ? cnt[i] : 0;
    sh[tid] = v;
    __syncthreads();
    for (int o = 1; o < 1024; o <<= 1) {
        int t = (tid >= o) ? sh[tid - o] : 0;
        __syncthreads();
        sh[tid] += t;
        __syncthreads();
    }
    if (i < N) excl[i] = sh[tid] - v;
    if (tid == 1023) bsum[blockIdx.x] = sh[1023];
}

// single-block exclusive scan of block sums (nb <= 1024)
__global__ void scan_sums(int* __restrict__ bsum, int nb) {
    __shared__ int sh[1024];
    int tid = threadIdx.x;
    int v = (tid < nb) ? bsum[tid] : 0;
    sh[tid] = v;
    __syncthreads();
    for (int o = 1; o < 1024; o <<= 1) {
        int t = (tid >= o) ? sh[tid - o] : 0;
        __syncthreads();
        sh[tid] += t;
        __syncthreads();
    }
    if (tid < nb) bsum[tid] = sh[tid] - v;
}

__global__ void add_offsets(int* __restrict__ excl, const int* __restrict__ bsum,
                            int N, int* __restrict__ cursor) {
    int i = blockIdx.x * blockDim.x + threadIdx.x;
    if (i < N) {
        int v = excl[i] + bsum[i >> 10];
        excl[i] = v;
        cursor[i] = v;
    }
}

__global__ void fill_csr(const int* __restrict__ src, const int* __restrict__ dst,
                         int E, int* __restrict__ cursor, int* __restrict__ csr) {
    int i = blockIdx.x * blockDim.x + threadIdx.x;
    if (i < E) {
        int p = atomicAdd(&cursor[dst[i]], 1);
        csr[p] = src[i];
    }
}

// ---------------- gather-based mean aggregation ----------------
// one warp per dst row: out[row] = mean over csr edges of feat[src]
__global__ void gather_agg(const float* __restrict__ feat, const int* __restrict__ csr,
                           const int* __restrict__ rowp, const int* __restrict__ cnt,
                           int N, float* __restrict__ out) {
    int row = blockIdx.x * (blockDim.x >> 5) + (threadIdx.x >> 5);
    int lane = threadIdx.x & 31;
    if (row >= N) return;
    int s = __ldg(&rowp[row]);
    int c = __ldg(&cnt[row]);
    float4 a0 = make_float4(0.f, 0.f, 0.f, 0.f);
    float4 a1 = make_float4(0.f, 0.f, 0.f, 0.f);
    int e = 0;
    for (; e + 1 < c; e += 2) {
        int s0 = __ldg(&csr[s + e]);
        int s1 = __ldg(&csr[s + e + 1]);
        float4 v0 = ((const float4*)(feat + (size_t)s0 * DIM))[lane];
        float4 v1 = ((const float4*)(feat + (size_t)s1 * DIM))[lane];
        a0.x += v0.x; a0.y += v0.y; a0.z += v0.z; a0.w += v0.w;
        a1.x += v1.x; a1.y += v1.y; a1.z += v1.z; a1.w += v1.w;
    }
    if (e < c) {
        int s0 = __ldg(&csr[s + e]);
        float4 v0 = ((const float4*)(feat + (size_t)s0 * DIM))[lane];
        a0.x += v0.x; a0.y += v0.y; a0.z += v0.z; a0.w += v0.w;
    }
    float inv = (c > 0) ? (1.0f / (float)c) : 0.0f;
    float4 o = make_float4((a0.x + a1.x) * inv, (a0.y + a1.y) * inv,
                           (a0.z + a1.z) * inv, (a0.w + a1.w) * inv);
    ((float4*)(out + (size_t)row * DIM))[lane] = o;
}

// ---------------- misc ----------------

__global__ void gather_rows(const float* __restrict__ emb, const int* __restrict__ ids,
                            int N, float* __restrict__ out) {
    int idx = blockIdx.x * blockDim.x + threadIdx.x;
    if (idx < N * 32) {
        int i = idx >> 5;
        int j = idx & 31;
        ((float4*)out)[idx] = ((const float4*)(emb + (size_t)ids[i] * DIM))[j];
    }
}

__global__ void prep_weights(const float* __restrict__ Wl, const float* __restrict__ bl,
                             const float* __restrict__ Wr, int l,
                             float* __restrict__ Bt_e, float* __restrict__ Bt_t,
                             float* __restrict__ Bt_y, float* __restrict__ bias_e,
                             float* __restrict__ bias_t) {
    int idx = blockIdx.x * blockDim.x + threadIdx.x;
    const float* Wl_l = Wl + (size_t)l * 3 * 16384;
    const float* Wr_l = Wr + (size_t)l * 3 * 16384;
    const float* bl_l = bl + (size_t)l * 3 * 128;
    if (idx < 32768) {                           // Bt_e
        int k = idx >> 7, j = idx & 127;
        if (k < 128)
            Bt_e[idx] = Wl_l[0 * 16384 + j * 128 + k];
        else
            Bt_e[idx] = Wr_l[0 * 16384 + j * 128 + (k - 128)] +
                        Wr_l[2 * 16384 + j * 128 + (k - 128)];
    } else if (idx < 65536) {                    // Bt_t
        int t = idx - 32768;
        int k = t >> 7, j = t & 127;
        if (k < 128)
            Bt_t[t] = Wl_l[1 * 16384 + j * 128 + k];
        else
            Bt_t[t] = Wr_l[1 * 16384 + j * 128 + (k - 128)];
    } else if (idx < 81920) {                    // Bt_y
        int t = idx - 65536;
        int k = t >> 7, j = t & 127;
        Bt_y[t] = Wl_l[2 * 16384 + j * 128 + k];
    } else if (idx < 81920 + 128) {
        int j = idx - 81920;
        bias_e[j] = bl_l[0 * 128 + j] + bl_l[2 * 128 + j];
    } else if (idx < 81920 + 256) {
        int j = idx - 82048;
        bias_t[j] = bl_l[1 * 128 + j];
    }
}

// ---------------- fused GEMM (f32x2 packed FMA inner loop) ----------------
// C[i][j] = sum_k<128 A1[i][k]*Bt[k][j] + (kseg==2) sum_k A2[i][k]*Bt[128+k][j]
//         + (addm) addm[i][j] + (bias) bias[j]
__global__ void __launch_bounds__(256)
gemm_fused(const float* __restrict__ A1, const float* __restrict__ A2,
           const float* __restrict__ Bt,
           const float* __restrict__ addm, const float* __restrict__ bias,
           float* __restrict__ C, int M, int kseg) {
    __shared__ float As[8][128];
    __shared__ float Bs[8][128];

    int tid = threadIdx.x;
    int tx = tid & 15, ty = tid >> 4;
    int row0 = blockIdx.x * 128;

    u64c acc2[8][4];
#pragma unroll
    for (int i = 0; i < 8; i++)
#pragma unroll
        for (int j = 0; j < 4; j++) acc2[i][j] = 0ULL;

    int ar = tid >> 1;                  // 0..127
    int ak4 = (tid & 1) * 4;            // 0 or 4
    int arow = row0 + ar;
    int bk = tid >> 5;                  // 0..7
    int bj = (tid & 31) * 4;            // 0..124

    int KT = kseg * 128;
    for (int k0 = 0; k0 < KT; k0 += 8) {
        float4 av = make_float4(0.f, 0.f, 0.f, 0.f);
        if (arow < M) {
            int k = k0 + ak4;
            if (k < 128)
                av = *(const float4*)(A1 + (size_t)arow * DIM + k);
            else
                av = *(const float4*)(A2 + (size_t)arow * DIM + (k - 128));
        }
        float4 bv = *(const float4*)(Bt + (size_t)(k0 + bk) * 128 + bj);

        __syncthreads();
        As[ak4 + 0][ar] = av.x;
        As[ak4 + 1][ar] = av.y;
        As[ak4 + 2][ar] = av.z;
        As[ak4 + 3][ar] = av.w;
        *(float4*)&Bs[bk][bj] = bv;
        __syncthreads();

#pragma unroll
        for (int kk = 0; kk < 8; kk++) {
            float4 a0 = *(float4*)&As[kk][ty * 4];
            float4 a1 = *(float4*)&As[kk][64 + ty * 4];
            float4 b0 = *(float4*)&Bs[kk][tx * 4];
            float4 b1 = *(float4*)&Bs[kk][64 + tx * 4];
            u64c bb[4];
            bb[0] = pk2(b0.x, b0.y);
            bb[1] = pk2(b0.z, b0.w);
            bb[2] = pk2(b1.x, b1.y);
            bb[3] = pk2(b1.z, b1.w);
            float a[8] = {a0.x, a0.y, a0.z, a0.w, a1.x, a1.y, a1.z, a1.w};
#pragma unroll
            for (int ri = 0; ri < 8; ri++) {
                u64c ap = pk2(a[ri], a[ri]);
#pragma unroll
                for (int cj = 0; cj < 4; cj++) fma2(acc2[ri][cj], ap, bb[cj]);
            }
        }
    }

    int c0 = tx * 4, c1 = 64 + tx * 4;
    float4 bia0 = make_float4(0.f, 0.f, 0.f, 0.f);
    float4 bia1 = make_float4(0.f, 0.f, 0.f, 0.f);
    if (bias) {
        bia0 = *(const float4*)(bias + c0);
        bia1 = *(const float4*)(bias + c1);
    }
#pragma unroll
    for (int ri = 0; ri < 8; ri++) {
        int rr = (ri < 4) ? (ty * 4 + ri) : (64 + ty * 4 + (ri - 4));
        int row = row0 + rr;
        if (row >= M) continue;
        float acc[8];
        upk2(acc2[ri][0], acc[0], acc[1]);
        upk2(acc2[ri][1], acc[2], acc[3]);
        upk2(acc2[ri][2], acc[4], acc[5]);
        upk2(acc2[ri][3], acc[6], acc[7]);
        float4 o0 = make_float4(acc[0] + bia0.x, acc[1] + bia0.y,
                                acc[2] + bia0.z, acc[3] + bia0.w);
        float4 o1 = make_float4(acc[4] + bia1.x, acc[5] + bia1.y,
                                acc[6] + bia1.z, acc[7] + bia1.w);
        if (addm) {
            float4 m0 = *(const float4*)(addm + (size_t)row * DIM + c0);
            float4 m1 = *(const float4*)(addm + (size_t)row * DIM + c1);
            o0.x += m0.x; o0.y += m0.y; o0.z += m0.z; o0.w += m0.w;
            o1.x += m1.x; o1.y += m1.y; o1.z += m1.z; o1.w += m1.w;
        }
        float* crow = C + (size_t)row * DIM;
        *(float4*)(crow + c0) = o0;
        *(float4*)(crow + c1) = o1;
    }
}

// ---------------- pooling ----------------
#define POOL_ROWS 512
__global__ void pool_kernel(const float* __restrict__ x, const int* __restrict__ batch,
                            int N, float* __restrict__ pooled) {
    int j = threadIdx.x;            // 0..127
    int r0 = blockIdx.x * POOL_ROWS;
    if (r0 >= N) return;
    int r1 = min(r0 + POOL_ROWS, N);
    float acc = 0.0f;
    int cur = batch[r0];
    for (int r = r0; r < r1; r++) {
        int b = batch[r];
        if (b != cur) {
            atomicAdd(&pooled[cur * DIM + j], acc);
            acc = 0.0f;
            cur = b;
        }
        acc += x[(size_t)r * DIM + j];
    }
    atomicAdd(&pooled[cur * DIM + j], acc);
}

// ---------------- MLP head ----------------
__global__ void mlp_kernel(const float* __restrict__ pooled,
                           const float* __restrict__ W1, const float* __restrict__ b1,
                           const float* __restrict__ W2, const float* __restrict__ b2,
                           float* __restrict__ out) {
    int b = blockIdx.x;
    int t = threadIdx.x;   // 128
    __shared__ float p[128], h[128];
    p[t] = pooled[b * DIM + t];
    __syncthreads();
    float acc = b1[t];
#pragma unroll 8
    for (int k = 0; k < 128; k++) acc += p[k] * W1[t * 128 + k];
    h[t] = fmaxf(acc, 0.0f);
    __syncthreads();
    if (t < OUT_DIM) {
        float o = b2[t];
#pragma unroll 8
        for (int k = 0; k < 128; k++) o += h[k] * W2[t * 128 + k];
        out[b * OUT_DIM + t] = o;
    }
}

// ---------------- driver ----------------
static void build_csr(const int* src, const int* dst, int E, int N,
                      int* cnt, int* rowp, int* cursor, int* bsum, int* csr) {
    cudaMemsetAsync(cnt, 0, (size_t)N * sizeof(int));
    degree_int<<<cdiv(E, 256), 256>>>(dst, E, cnt);
    int nb = cdiv(N, 1024);
    scan_block<<<nb, 1024>>>(cnt, N, rowp, bsum);
    scan_sums<<<1, 1024>>>(bsum, nb);
    add_offsets<<<cdiv(N, 256), 256>>>(rowp, bsum, N, cursor);
    fill_csr<<<cdiv(E, 256), 256>>>(src, dst, E, cursor, csr);
}

extern "C" void kernel_launch(void* const* d_in, const int* in_sizes, int n_in,
                              void* d_out, int out_size) {
    const int* event_ids   = (const int*)d_in[0];
    const int* trace_ids   = (const int*)d_in[1];
    const int* e2e_src     = (const int*)d_in[2];
    const int* e2e_dst     = (const int*)d_in[3];
    const int* e2t_src     = (const int*)d_in[4];
    const int* e2t_dst     = (const int*)d_in[5];
    const int* t2e_src     = (const int*)d_in[6];
    const int* t2e_dst     = (const int*)d_in[7];
    const int* event_batch = (const int*)d_in[8];
    const int* trace_batch = (const int*)d_in[9];
    const float* emb_event = (const float*)d_in[10];
    const float* emb_trace = (const float*)d_in[11];
    const float* Wl        = (const float*)d_in[12];
    const float* bl        = (const float*)d_in[13];
    const float* Wr        = (const float*)d_in[14];
    const float* W1        = (const float*)d_in[15];
    const float* b1        = (const float*)d_in[16];
    const float* W2        = (const float*)d_in[17];
    const float* b2        = (const float*)d_in[18];

    const int Ne  = in_sizes[0];
    const int Nt  = in_sizes[1];
    const int Eee = in_sizes[2];
    const int Eet = in_sizes[4];
    const int Ete = in_sizes[6];

    float *xe[2], *xt[2], *agg_ee, *agg_te, *agg_et, *yt;
    float *Bt_e, *Bt_t, *Bt_y, *bias_e, *bias_t, *pooled;
    int *cnt_ee, *cnt_te, *cnt_et, *rowp_ee, *rowp_te, *rowp_et;
    int *cur_ee, *cur_te, *cur_et, *bs_ee, *bs_te, *bs_et;
    int *csr_ee, *csr_te, *csr_et;
    cudaGetSymbolAddress((void**)&xe[0], g_xe0);
    cudaGetSymbolAddress((void**)&xe[1], g_xe1);
    cudaGetSymbolAddress((void**)&xt[0], g_xt0);
    cudaGetSymbolAddress((void**)&xt[1], g_xt1);
    cudaGetSymbolAddress((void**)&agg_ee, g_agg_ee);
    cudaGetSymbolAddress((void**)&agg_te, g_agg_te);
    cudaGetSymbolAddress((void**)&agg_et, g_agg_et);
    cudaGetSymbolAddress((void**)&yt, g_yt);
    cudaGetSymbolAddress((void**)&cnt_ee, g_cnt_ee);
    cudaGetSymbolAddress((void**)&cnt_te, g_cnt_te);
    cudaGetSymbolAddress((void**)&cnt_et, g_cnt_et);
    cudaGetSymbolAddress((void**)&rowp_ee, g_rowp_ee);
    cudaGetSymbolAddress((void**)&rowp_te, g_rowp_te);
    cudaGetSymbolAddress((void**)&rowp_et, g_rowp_et);
    cudaGetSymbolAddress((void**)&cur_ee, g_cur_ee);
    cudaGetSymbolAddress((void**)&cur_te, g_cur_te);
    cudaGetSymbolAddress((void**)&cur_et, g_cur_et);
    cudaGetSymbolAddress((void**)&bs_ee, g_bsum_ee);
    cudaGetSymbolAddress((void**)&bs_te, g_bsum_te);
    cudaGetSymbolAddress((void**)&bs_et, g_bsum_et);
    cudaGetSymbolAddress((void**)&csr_ee, g_csr_ee);
    cudaGetSymbolAddress((void**)&csr_te, g_csr_te);
    cudaGetSymbolAddress((void**)&csr_et, g_csr_et);
    cudaGetSymbolAddress((void**)&Bt_e, g_Bt_e);
    cudaGetSymbolAddress((void**)&Bt_t, g_Bt_t);
    cudaGetSymbolAddress((void**)&Bt_y, g_Bt_y);
    cudaGetSymbolAddress((void**)&bias_e, g_bias_e);
    cudaGetSymbolAddress((void**)&bias_t, g_bias_t);
    cudaGetSymbolAddress((void**)&pooled, g_pooled);

    cudaMemsetAsync(pooled, 0, (size_t)B_GRAPH * DIM * sizeof(float));

    // ---- CSR build (layer-invariant) ----
    build_csr(e2e_src, e2e_dst, Eee, Ne, cnt_ee, rowp_ee, cur_ee, bs_ee, csr_ee);
    build_csr(t2e_src, t2e_dst, Ete, Ne, cnt_te, rowp_te, cur_te, bs_te, csr_te);
    build_csr(e2t_src, e2t_dst, Eet, Nt, cnt_et, rowp_et, cur_et, bs_et, csr_et);

    // ---- initial embeddings ----
    gather_rows<<<cdiv(Ne * 32, 256), 256>>>(emb_event, event_ids, Ne, xe[0]);
    gather_rows<<<cdiv(Nt * 32, 256), 256>>>(emb_trace, trace_ids, Nt, xt[0]);

    int cur = 0;
    for (int l = 0; l < 3; l++) {
        prep_weights<<<cdiv(82176, 256), 256>>>(Wl, bl, Wr, l, Bt_e, Bt_t, Bt_y, bias_e, bias_t);

        // transform-first for trace->event: y = x_trace @ Wl2.T
        gemm_fused<<<cdiv(Nt, 128), 256>>>(xt[cur], nullptr, Bt_y,
                                           nullptr, nullptr, yt, Nt, 1);

        // mean aggregations (gather over CSR; mean applied in-register)
        gather_agg<<<cdiv(Ne, 8), 256>>>(xe[cur], csr_ee, rowp_ee, cnt_ee, Ne, agg_ee);
        gather_agg<<<cdiv(Nt, 8), 256>>>(xe[cur], csr_et, rowp_et, cnt_et, Nt, agg_et);
        gather_agg<<<cdiv(Ne, 8), 256>>>(yt,      csr_te, rowp_te, cnt_te, Ne, agg_te);

        // event: mean_ee@Wl0.T + x_e@(Wr0+Wr2).T + mean_te_y + (bl0+bl2)
        gemm_fused<<<cdiv(Ne, 128), 256>>>(agg_ee, xe[cur], Bt_e,
                                           agg_te, bias_e, xe[1 - cur], Ne, 2);
        // trace: mean_et@Wl1.T + x_t@Wr1.T + bl1
        gemm_fused<<<cdiv(Nt, 128), 256>>>(agg_et, xt[cur], Bt_t,
                                           nullptr, bias_t, xt[1 - cur], Nt, 2);
        cur ^= 1;
    }

    // ---- pooling + head ----
    pool_kernel<<<cdiv(Ne, POOL_ROWS), 128>>>(xe[cur], event_batch, Ne, pooled);
    pool_kernel<<<cdiv(Nt, POOL_ROWS), 128>>>(xt[cur], trace_batch, Nt, pooled);
    mlp_kernel<<<B_GRAPH, 128>>>(pooled, W1, b1, W2, b2, (float*)d_out);
}

// round 6
// speedup vs baseline: 2.4757x; 1.2585x over previous
#include <cuda_runtime.h>
#include <cuda_bf16.h>
#include <cstdint>

#define N_EVENT_C 100000
#define N_TRACE_C 20000
#define E_EE_C 1000000
#define E_ET_C 500000
#define E_TE_C 500000
#define DIM 128
#define B_GRAPH 64
#define OUT_DIM 64

// ---------------- scratch (device globals) ----------------
__device__ float g_xe0[N_EVENT_C * DIM];
__device__ float g_xe1[N_EVENT_C * DIM];
__device__ float g_xt0[N_TRACE_C * DIM];
__device__ float g_xt1[N_TRACE_C * DIM];
__device__ float g_agg_ee[N_EVENT_C * DIM];
__device__ float g_agg_te[N_EVENT_C * DIM];
__device__ float g_agg_et[N_TRACE_C * DIM];
__device__ float g_yt[N_TRACE_C * DIM];

__device__ int g_cnt_ee[N_EVENT_C];
__device__ int g_cnt_te[N_EVENT_C];
__device__ int g_cnt_et[N_TRACE_C];
__device__ int g_rowp_ee[N_EVENT_C];
__device__ int g_rowp_te[N_EVENT_C];
__device__ int g_rowp_et[N_TRACE_C];
__device__ int g_cur_ee[N_EVENT_C];
__device__ int g_cur_te[N_EVENT_C];
__device__ int g_cur_et[N_TRACE_C];
__device__ int g_bsum_ee[1024];
__device__ int g_bsum_te[1024];
__device__ int g_bsum_et[1024];
__device__ int g_csr_ee[E_EE_C];
__device__ int g_csr_te[E_TE_C];
__device__ int g_csr_et[E_ET_C];

// packed bf16 hi/lo weights, xor-swizzled [n][k] layout.
// slot s (0..4): [hi 32768 B][lo 32768 B]
// slots: 0=Wl0, 1=Wr0+Wr2, 2=Wl1, 3=Wr1, 4=Wl2
__device__ __align__(16) unsigned char g_Wpk[5 * 65536];
__device__ float g_bias_e[128];
__device__ float g_pooled[B_GRAPH * DIM];

static inline int cdiv(int a, int b) { return (a + b - 1) / b; }

// ---------------- bf16 split helper ----------------
__device__ __forceinline__ void split2(float a, float b, uint32_t& hi, uint32_t& lo) {
    __nv_bfloat16 ha = __float2bfloat16(a), hb = __float2bfloat16(b);
    float ra = a - __bfloat162float(ha);
    float rb = b - __bfloat162float(hb);
    __nv_bfloat16 la = __float2bfloat16(ra), lb = __float2bfloat16(rb);
    unsigned short hau = *reinterpret_cast<unsigned short*>(&ha);
    unsigned short hbu = *reinterpret_cast<unsigned short*>(&hb);
    unsigned short lau = *reinterpret_cast<unsigned short*>(&la);
    unsigned short lbu = *reinterpret_cast<unsigned short*>(&lb);
    hi = ((uint32_t)hbu << 16) | hau;
    lo = ((uint32_t)lbu << 16) | lau;
}

// xor-swizzled byte offset within a 128n x 128k bf16 plane (row stride 256B):
// 16B chunk index (k>>3) xored with (n&7) -> conflict-free ldmatrix
__device__ __forceinline__ uint32_t wswz(int n, int k) {
    return (uint32_t)(n * 256 + ((((k >> 3) ^ (n & 7)) << 4) | ((k & 7) * 2)));
}

// ---------------- PTX helpers ----------------
__device__ __forceinline__ uint32_t smem_u32(const void* p) {
    uint32_t a;
    asm("{ .reg .u64 t; cvta.to.shared.u64 t, %1; cvt.u32.u64 %0, t; }" : "=r"(a) : "l"(p));
    return a;
}
__device__ __forceinline__ void ldmx4(uint32_t& r0, uint32_t& r1, uint32_t& r2, uint32_t& r3,
                                      uint32_t addr) {
    asm volatile("ldmatrix.sync.aligned.m8n8.x4.shared.b16 {%0,%1,%2,%3}, [%4];"
                 : "=r"(r0), "=r"(r1), "=r"(r2), "=r"(r3) : "r"(addr));
}
__device__ __forceinline__ void mma16816(float* d, const uint32_t* a, const uint32_t* b) {
    asm volatile(
        "mma.sync.aligned.m16n8k16.row.col.f32.bf16.bf16.f32 "
        "{%0,%1,%2,%3}, {%4,%5,%6,%7}, {%8,%9}, {%0,%1,%2,%3};"
        : "+f"(d[0]), "+f"(d[1]), "+f"(d[2]), "+f"(d[3])
        : "r"(a[0]), "r"(a[1]), "r"(a[2]), "r"(a[3]), "r"(b[0]), "r"(b[1]));
}

// ---------------- CSR build kernels ----------------
__global__ void degree_int(const int* __restrict__ dst, int E, int* __restrict__ cnt) {
    int i = blockIdx.x * blockDim.x + threadIdx.x;
    if (i < E) atomicAdd(&cnt[dst[i]], 1);
}

__global__ void scan_block(const int* __restrict__ cnt, int N,
                           int* __restrict__ excl, int* __restrict__ bsum) {
    __shared__ int sh[1024];
    int tid = threadIdx.x;
    int i = blockIdx.x * 1024 + tid;
    int v = (i < N) ? cnt[i] : 0;
    sh[tid] = v;
    __syncthreads();
    for (int o = 1; o < 1024; o <<= 1) {
        int t = (tid >= o) ? sh[tid - o] : 0;
        __syncthreads();
        sh[tid] += t;
        __syncthreads();
    }
    if (i < N) excl[i] = sh[tid] - v;
    if (tid == 1023) bsum[blockIdx.x] = sh[1023];
}

__global__ void scan_sums(int* __restrict__ bsum, int nb) {
    __shared__ int sh[1024];
    int tid = threadIdx.x;
    int v = (tid < nb) ? bsum[tid] : 0;
    sh[tid] = v;
    __syncthreads();
    for (int o = 1; o < 1024; o <<= 1) {
        int t = (tid >= o) ? sh[tid - o] : 0;
        __syncthreads();
        sh[tid] += t;
        __syncthreads();
    }
    if (tid < nb) bsum[tid] = sh[tid] - v;
}

__global__ void add_offsets(int* __restrict__ excl, const int* __restrict__ bsum,
                            int N, int* __restrict__ cursor) {
    int i = blockIdx.x * blockDim.x + threadIdx.x;
    if (i < N) {
        int v = excl[i] + bsum[i >> 10];
        excl[i] = v;
        cursor[i] = v;
    }
}

__global__ void fill_csr(const int* __restrict__ src, const int* __restrict__ dst,
                         int E, int* __restrict__ cursor, int* __restrict__ csr) {
    int i = blockIdx.x * blockDim.x + threadIdx.x;
    if (i < E) {
        int p = atomicAdd(&cursor[dst[i]], 1);
        csr[p] = src[i];
    }
}

// ---------------- gather-based mean aggregation ----------------
__global__ void gather_agg(const float* __restrict__ feat, const int* __restrict__ csr,
                           const int* __restrict__ rowp, const int* __restrict__ cnt,
                           int N, float* __restrict__ out) {
    int row = blockIdx.x * (blockDim.x >> 5) + (threadIdx.x >> 5);
    int lane = threadIdx.x & 31;
    if (row >= N) return;
    int s = __ldg(&rowp[row]);
    int c = __ldg(&cnt[row]);
    float4 a0 = make_float4(0.f, 0.f, 0.f, 0.f);
    float4 a1 = make_float4(0.f, 0.f, 0.f, 0.f);
    int e = 0;
    for (; e + 1 < c; e += 2) {
        int s0 = __ldg(&csr[s + e]);
        int s1 = __ldg(&csr[s + e + 1]);
        float4 v0 = ((const float4*)(feat + (size_t)s0 * DIM))[lane];
        float4 v1 = ((const float4*)(feat + (size_t)s1 * DIM))[lane];
        a0.x += v0.x; a0.y += v0.y; a0.z += v0.z; a0.w += v0.w;
        a1.x += v1.x; a1.y += v1.y; a1.z += v1.z; a1.w += v1.w;
    }
    if (e < c) {
        int s0 = __ldg(&csr[s + e]);
        float4 v0 = ((const float4*)(feat + (size_t)s0 * DIM))[lane];
        a0.x += v0.x; a0.y += v0.y; a0.z += v0.z; a0.w += v0.w;
    }
    float inv = (c > 0) ? (1.0f / (float)c) : 0.0f;
    float4 o = make_float4((a0.x + a1.x) * inv, (a0.y + a1.y) * inv,
                           (a0.z + a1.z) * inv, (a0.w + a1.w) * inv);
    ((float4*)(out + (size_t)row * DIM))[lane] = o;
}

// ---------------- misc ----------------
__global__ void gather_rows(const float* __restrict__ emb, const int* __restrict__ ids,
                            int N, float* __restrict__ out) {
    int idx = blockIdx.x * blockDim.x + threadIdx.x;
    if (idx < N * 32) {
        int i = idx >> 5;
        int j = idx & 31;
        ((float4*)out)[idx] = ((const float4*)(emb + (size_t)ids[i] * DIM))[j];
    }
}

// per-layer weight split/pack: [n][k] fp32 -> bf16 hi/lo planes, xor-swizzled
__global__ void prep_wpk(const float* __restrict__ Wl, const float* __restrict__ bl,
                         const float* __restrict__ Wr, int l,
                         unsigned char* __restrict__ Wpk, float* __restrict__ bias_e) {
    int idx = blockIdx.x * blockDim.x + threadIdx.x;
    const float* Wl_l = Wl + (size_t)l * 3 * 16384;
    const float* Wr_l = Wr + (size_t)l * 3 * 16384;
    if (idx < 40960) {
        int mat = idx >> 13;        // 0..4
        int rem = idx & 8191;
        int n = rem >> 6;           // 0..127
        int k = (rem & 63) << 1;    // even k
        float v0, v1;
        switch (mat) {
            case 0: v0 = Wl_l[n * 128 + k]; v1 = Wl_l[n * 128 + k + 1]; break;
            case 1: v0 = Wr_l[n * 128 + k] + Wr_l[2 * 16384 + n * 128 + k];
                    v1 = Wr_l[n * 128 + k + 1] + Wr_l[2 * 16384 + n * 128 + k + 1]; break;
            case 2: v0 = Wl_l[16384 + n * 128 + k]; v1 = Wl_l[16384 + n * 128 + k + 1]; break;
            case 3: v0 = Wr_l[16384 + n * 128 + k]; v1 = Wr_l[16384 + n * 128 + k + 1]; break;
            default: v0 = Wl_l[2 * 16384 + n * 128 + k];
                     v1 = Wl_l[2 * 16384 + n * 128 + k + 1]; break;
        }
        uint32_t hp, lp;
        split2(v0, v1, hp, lp);
        uint32_t o = wswz(n, k);
        *(uint32_t*)(Wpk + (size_t)mat * 65536 + o) = hp;
        *(uint32_t*)(Wpk + (size_t)mat * 65536 + 32768 + o) = lp;
    } else if (idx < 41088) {
        int j = idx - 40960;
        const float* bl_l = bl + (size_t)l * 3 * 128;
        bias_e[j] = bl_l[j] + bl_l[2 * 128 + j];
    }
}

// ---------------- tensor-core GEMM (bf16 split via mma.sync) ----------------
// C[i][j] = sum over chunks: A_c[i][:] @ W_c[j][:] (+ addm[i][j]) (+ bias[j])
// A fp32 from global (split in registers), W pre-split bf16 hi/lo in smem.
#define GM_SMEM 65536
__global__ void __launch_bounds__(256)
gemm_mma(const float* __restrict__ A0, const unsigned char* __restrict__ W0,
         const float* __restrict__ A1, const unsigned char* __restrict__ W1,
         const float* __restrict__ addm, const float* __restrict__ bias,
         float* __restrict__ C, int M, int nchunks) {
    extern __shared__ unsigned char bs[];    // [hi 32KB][lo 32KB]
    int tid = threadIdx.x;
    int lane = tid & 31;
    int wid = tid >> 5;
    int mr = wid >> 1;                // warp row 0..3
    int nc = wid & 1;                 // warp col 0..1
    int row_base = blockIdx.x * 128 + mr * 32;
    int q = lane & 3;                 // quad
    int grp = lane >> 2;              // 0..7

    // B ldmatrix per-thread pieces
    int bn_local = ((lane >> 4) << 3) + (lane & 7);  // n offset within 16-n group
    int koff8 = ((lane >> 3) & 1) << 3;              // 0 or 8
    uint32_t sB = smem_u32(bs);

    float acc[2][8][4];
#pragma unroll
    for (int i = 0; i < 2; i++)
#pragma unroll
        for (int j = 0; j < 8; j++)
#pragma unroll
            for (int v = 0; v < 4; v++) acc[i][j][v] = 0.0f;

    for (int c = 0; c < nchunks; c++) {
        const float* Ap = c ? A1 : A0;
        const unsigned char* Wp = c ? W1 : W0;
        __syncthreads();
        // copy 64KB of pre-swizzled B (hi+lo planes)
#pragma unroll
        for (int i = 0; i < 16; i++) {
            int e = i * 256 + tid;
            ((uint4*)bs)[e] = __ldg(&((const uint4*)Wp)[e]);
        }
        __syncthreads();

#pragma unroll
        for (int kk = 0; kk < 8; kk++) {
            int kb = kk * 16;
            // B fragments (hi & lo) for this warp's 8 n-tiles
            uint32_t Bh[8][2], Bl[8][2];
#pragma unroll
            for (int p = 0; p < 4; p++) {
                int n = nc * 64 + p * 16 + bn_local;
                int k = kb + koff8;
                uint32_t off = (uint32_t)(n * 256 + ((((k >> 3) ^ (n & 7)) << 4)));
                uint32_t r0, r1, r2, r3;
                ldmx4(r0, r1, r2, r3, sB + off);
                Bh[p * 2][0] = r0; Bh[p * 2][1] = r1;
                Bh[p * 2 + 1][0] = r2; Bh[p * 2 + 1][1] = r3;
                ldmx4(r0, r1, r2, r3, sB + 32768 + off);
                Bl[p * 2][0] = r0; Bl[p * 2][1] = r1;
                Bl[p * 2 + 1][0] = r2; Bl[p * 2 + 1][1] = r3;
            }
            // A fragments direct from global fp32, split to bf16 hi/lo
            uint32_t Ah[2][4], Al[2][4];
#pragma unroll
            for (int i = 0; i < 2; i++) {
                int rl = row_base + i * 16 + grp;
                int rh = rl + 8;
                int rlc = min(rl, M - 1);
                int rhc = min(rh, M - 1);
                int k0 = kb + 2 * q;
                float2 v00 = __ldg((const float2*)(Ap + (size_t)rlc * DIM + k0));
                float2 v10 = __ldg((const float2*)(Ap + (size_t)rhc * DIM + k0));
                float2 v01 = __ldg((const float2*)(Ap + (size_t)rlc * DIM + k0 + 8));
                float2 v11 = __ldg((const float2*)(Ap + (size_t)rhc * DIM + k0 + 8));
                split2(v00.x, v00.y, Ah[i][0], Al[i][0]);
                split2(v10.x, v10.y, Ah[i][1], Al[i][1]);
                split2(v01.x, v01.y, Ah[i][2], Al[i][2]);
                split2(v11.x, v11.y, Ah[i][3], Al[i][3]);
            }
            // 3-product MMAs
#pragma unroll
            for (int i = 0; i < 2; i++)
#pragma unroll
                for (int j = 0; j < 8; j++) {
                    mma16816(acc[i][j], Ah[i], Bh[j]);
                    mma16816(acc[i][j], Al[i], Bh[j]);
                    mma16816(acc[i][j], Ah[i], Bl[j]);
                }
        }
    }

    // epilogue
#pragma unroll
    for (int i = 0; i < 2; i++) {
        int R0 = row_base + i * 16 + grp;
        int R1 = R0 + 8;
#pragma unroll
        for (int j = 0; j < 8; j++) {
            int Cc = nc * 64 + j * 8 + 2 * q;
            float2 o0 = make_float2(acc[i][j][0], acc[i][j][1]);
            float2 o1 = make_float2(acc[i][j][2], acc[i][j][3]);
            if (bias) {
                float2 bv = *(const float2*)(bias + Cc);
                o0.x += bv.x; o0.y += bv.y;
                o1.x += bv.x; o1.y += bv.y;
            }
            if (R0 < M) {
                if (addm) {
                    float2 m0 = *(const float2*)(addm + (size_t)R0 * DIM + Cc);
                    o0.x += m0.x; o0.y += m0.y;
                }
                *(float2*)(C + (size_t)R0 * DIM + Cc) = o0;
            }
            if (R1 < M) {
                if (addm) {
                    float2 m1 = *(const float2*)(addm + (size_t)R1 * DIM + Cc);
                    o1.x += m1.x; o1.y += m1.y;
                }
                *(float2*)(C + (size_t)R1 * DIM + Cc) = o1;
            }
        }
    }
}

// ---------------- pooling ----------------
#define POOL_ROWS 512
__global__ void pool_kernel(const float* __restrict__ x, const int* __restrict__ batch,
                            int N, float* __restrict__ pooled) {
    int j = threadIdx.x;
    int r0 = blockIdx.x * POOL_ROWS;
    if (r0 >= N) return;
    int r1 = min(r0 + POOL_ROWS, N);
    float acc = 0.0f;
    int cur = batch[r0];
    for (int r = r0; r < r1; r++) {
        int b = batch[r];
        if (b != cur) {
            atomicAdd(&pooled[cur * DIM + j], acc);
            acc = 0.0f;
            cur = b;
        }
        acc += x[(size_t)r * DIM + j];
    }
    atomicAdd(&pooled[cur * DIM + j], acc);
}

// ---------------- MLP head ----------------
__global__ void mlp_kernel(const float* __restrict__ pooled,
                           const float* __restrict__ W1, const float* __restrict__ b1,
                           const float* __restrict__ W2, const float* __restrict__ b2,
                           float* __restrict__ out) {
    int b = blockIdx.x;
    int t = threadIdx.x;
    __shared__ float p[128], h[128];
    p[t] = pooled[b * DIM + t];
    __syncthreads();
    float acc = b1[t];
#pragma unroll 8
    for (int k = 0; k < 128; k++) acc += p[k] * W1[t * 128 + k];
    h[t] = fmaxf(acc, 0.0f);
    __syncthreads();
    if (t < OUT_DIM) {
        float o = b2[t];
#pragma unroll 8
        for (int k = 0; k < 128; k++) o += h[k] * W2[t * 128 + k];
        out[b * OUT_DIM + t] = o;
    }
}

// ---------------- driver ----------------
static void build_csr(const int* src, const int* dst, int E, int N,
                      int* cnt, int* rowp, int* cursor, int* bsum, int* csr) {
    cudaMemsetAsync(cnt, 0, (size_t)N * sizeof(int));
    degree_int<<<cdiv(E, 256), 256>>>(dst, E, cnt);
    int nb = cdiv(N, 1024);
    scan_block<<<nb, 1024>>>(cnt, N, rowp, bsum);
    scan_sums<<<1, 1024>>>(bsum, nb);
    add_offsets<<<cdiv(N, 256), 256>>>(rowp, bsum, N, cursor);
    fill_csr<<<cdiv(E, 256), 256>>>(src, dst, E, cursor, csr);
}

extern "C" void kernel_launch(void* const* d_in, const int* in_sizes, int n_in,
                              void* d_out, int out_size) {
    const int* event_ids   = (const int*)d_in[0];
    const int* trace_ids   = (const int*)d_in[1];
    const int* e2e_src     = (const int*)d_in[2];
    const int* e2e_dst     = (const int*)d_in[3];
    const int* e2t_src     = (const int*)d_in[4];
    const int* e2t_dst     = (const int*)d_in[5];
    const int* t2e_src     = (const int*)d_in[6];
    const int* t2e_dst     = (const int*)d_in[7];
    const int* event_batch = (const int*)d_in[8];
    const int* trace_batch = (const int*)d_in[9];
    const float* emb_event = (const float*)d_in[10];
    const float* emb_trace = (const float*)d_in[11];
    const float* Wl        = (const float*)d_in[12];
    const float* bl        = (const float*)d_in[13];
    const float* Wr        = (const float*)d_in[14];
    const float* W1        = (const float*)d_in[15];
    const float* b1        = (const float*)d_in[16];
    const float* W2        = (const float*)d_in[17];
    const float* b2        = (const float*)d_in[18];

    const int Ne  = in_sizes[0];
    const int Nt  = in_sizes[1];
    const int Eee = in_sizes[2];
    const int Eet = in_sizes[4];
    const int Ete = in_sizes[6];

    float *xe[2], *xt[2], *agg_ee, *agg_te, *agg_et, *yt, *bias_e, *pooled;
    unsigned char* Wpk;
    int *cnt_ee, *cnt_te, *cnt_et, *rowp_ee, *rowp_te, *rowp_et;
    int *cur_ee, *cur_te, *cur_et, *bs_ee, *bs_te, *bs_et;
    int *csr_ee, *csr_te, *csr_et;
    cudaGetSymbolAddress((void**)&xe[0], g_xe0);
    cudaGetSymbolAddress((void**)&xe[1], g_xe1);
    cudaGetSymbolAddress((void**)&xt[0], g_xt0);
    cudaGetSymbolAddress((void**)&xt[1], g_xt1);
    cudaGetSymbolAddress((void**)&agg_ee, g_agg_ee);
    cudaGetSymbolAddress((void**)&agg_te, g_agg_te);
    cudaGetSymbolAddress((void**)&agg_et, g_agg_et);
    cudaGetSymbolAddress((void**)&yt, g_yt);
    cudaGetSymbolAddress((void**)&cnt_ee, g_cnt_ee);
    cudaGetSymbolAddress((void**)&cnt_te, g_cnt_te);
    cudaGetSymbolAddress((void**)&cnt_et, g_cnt_et);
    cudaGetSymbolAddress((void**)&rowp_ee, g_rowp_ee);
    cudaGetSymbolAddress((void**)&rowp_te, g_rowp_te);
    cudaGetSymbolAddress((void**)&rowp_et, g_rowp_et);
    cudaGetSymbolAddress((void**)&cur_ee, g_cur_ee);
    cudaGetSymbolAddress((void**)&cur_te, g_cur_te);
    cudaGetSymbolAddress((void**)&cur_et, g_cur_et);
    cudaGetSymbolAddress((void**)&bs_ee, g_bsum_ee);
    cudaGetSymbolAddress((void**)&bs_te, g_bsum_te);
    cudaGetSymbolAddress((void**)&bs_et, g_bsum_et);
    cudaGetSymbolAddress((void**)&csr_ee, g_csr_ee);
    cudaGetSymbolAddress((void**)&csr_te, g_csr_te);
    cudaGetSymbolAddress((void**)&csr_et, g_csr_et);
    cudaGetSymbolAddress((void**)&Wpk, g_Wpk);
    cudaGetSymbolAddress((void**)&bias_e, g_bias_e);
    cudaGetSymbolAddress((void**)&pooled, g_pooled);

    cudaFuncSetAttribute(gemm_mma, cudaFuncAttributeMaxDynamicSharedMemorySize, GM_SMEM);

    cudaMemsetAsync(pooled, 0, (size_t)B_GRAPH * DIM * sizeof(float));

    // ---- CSR build (layer-invariant) ----
    build_csr(e2e_src, e2e_dst, Eee, Ne, cnt_ee, rowp_ee, cur_ee, bs_ee, csr_ee);
    build_csr(t2e_src, t2e_dst, Ete, Ne, cnt_te, rowp_te, cur_te, bs_te, csr_te);
    build_csr(e2t_src, e2t_dst, Eet, Nt, cnt_et, rowp_et, cur_et, bs_et, csr_et);

    // ---- initial embeddings ----
    gather_rows<<<cdiv(Ne * 32, 256), 256>>>(emb_event, event_ids, Ne, xe[0]);
    gather_rows<<<cdiv(Nt * 32, 256), 256>>>(emb_trace, trace_ids, Nt, xt[0]);

    int cur = 0;
    for (int l = 0; l < 3; l++) {
        prep_wpk<<<cdiv(41088, 256), 256>>>(Wl, bl, Wr, l, Wpk, bias_e);
        const float* bias_t = bl + ((size_t)l * 3 + 1) * 128;

        // transform-first for trace->event: y = x_trace @ Wl2.T
        gemm_mma<<<cdiv(Nt, 128), 256, GM_SMEM>>>(
            xt[cur], Wpk + 4 * 65536, nullptr, nullptr,
            nullptr, nullptr, yt, Nt, 1);

        // mean aggregations (gather over CSR)
        gather_agg<<<cdiv(Ne, 8), 256>>>(xe[cur], csr_ee, rowp_ee, cnt_ee, Ne, agg_ee);
        gather_agg<<<cdiv(Nt, 8), 256>>>(xe[cur], csr_et, rowp_et, cnt_et, Nt, agg_et);
        gather_agg<<<cdiv(Ne, 8), 256>>>(yt,      csr_te, rowp_te, cnt_te, Ne, agg_te);

        // event: mean_ee@Wl0.T + x_e@(Wr0+Wr2).T + mean_te_y + (bl0+bl2)
        gemm_mma<<<cdiv(Ne, 128), 256, GM_SMEM>>>(
            agg_ee, Wpk + 0 * 65536, xe[cur], Wpk + 1 * 65536,
            agg_te, bias_e, xe[1 - cur], Ne, 2);
        // trace: mean_et@Wl1.T + x_t@Wr1.T + bl1
        gemm_mma<<<cdiv(Nt, 128), 256, GM_SMEM>>>(
            agg_et, Wpk + 2 * 65536, xt[cur], Wpk + 3 * 65536,
            nullptr, bias_t, xt[1 - cur], Nt, 2);
        cur ^= 1;
    }

    // ---- pooling + head ----
    pool_kernel<<<cdiv(Ne, POOL_ROWS), 128>>>(xe[cur], event_batch, Ne, pooled);
    pool_kernel<<<cdiv(Nt, POOL_ROWS), 128>>>(xt[cur], trace_batch, Nt, pooled);
    mlp_kernel<<<B_GRAPH, 128>>>(pooled, W1, b1, W2, b2, (float*)d_out);
}